// round 1
// baseline (speedup 1.0000x reference)
#include <cuda_runtime.h>
#include <math.h>

// Problem constants
#define SEQ   4096
#define DMODEL 1024
#define NHEAD 16
#define DHEAD 64

// Scratch (allocation-free: __device__ globals)
__device__ float g_q[(size_t)NHEAD * SEQ * DHEAD];
__device__ float g_k[(size_t)NHEAD * SEQ * DHEAD];
__device__ float g_v[(size_t)NHEAD * SEQ * DHEAD];
__device__ float g_z[(size_t)SEQ * DMODEL];

// ---------------------------------------------------------------------------
// SGEMM: C = A[4096,1024] * B[1024,1024]^T
//   A row-major [M=4096, K=1024], B row-major [N=1024, K=1024]
//   mode 0: C[s*1024 + n]                       (plain row-major)
//   mode 1: C[((n>>6)*SEQ + s)*64 + (n&63)]     (per-head [H][S][64] layout)
// Tiles: BM=128, BN=64, BK=16; 256 threads; TM=8, TN=4 per thread.
// ---------------------------------------------------------------------------
__global__ __launch_bounds__(256) void sgemm_kernel(
    const float* __restrict__ A, const float* __restrict__ B,
    float* __restrict__ C, int mode)
{
    __shared__ float As[16][128];   // k-major
    __shared__ float Bs[16][64];    // k-major

    const int tid = threadIdx.x;
    const int tx = tid & 15;        // n direction (TN=4 -> 64)
    const int ty = tid >> 4;        // m direction (TM=8 -> 128)
    const int m0 = blockIdx.x * 128;
    const int n0 = blockIdx.y * 64;

    float acc[8][4];
#pragma unroll
    for (int i = 0; i < 8; ++i)
#pragma unroll
        for (int j = 0; j < 4; ++j) acc[i][j] = 0.0f;

    for (int k0 = 0; k0 < 1024; k0 += 16) {
        // Load A tile (128x16) transposed into As[k][m]
#pragma unroll
        for (int r = 0; r < 2; ++r) {
            int idx = tid + r * 256;            // 512 float4 loads
            int row = idx >> 2;
            int c4  = idx & 3;
            float4 v = *(const float4*)(A + (size_t)(m0 + row) * 1024 + k0 + c4 * 4);
            As[c4 * 4 + 0][row] = v.x;
            As[c4 * 4 + 1][row] = v.y;
            As[c4 * 4 + 2][row] = v.z;
            As[c4 * 4 + 3][row] = v.w;
        }
        // Load B tile (64x16) transposed into Bs[k][n]
        {
            int row = tid >> 2;
            int c4  = tid & 3;
            float4 v = *(const float4*)(B + (size_t)(n0 + row) * 1024 + k0 + c4 * 4);
            Bs[c4 * 4 + 0][row] = v.x;
            Bs[c4 * 4 + 1][row] = v.y;
            Bs[c4 * 4 + 2][row] = v.z;
            Bs[c4 * 4 + 3][row] = v.w;
        }
        __syncthreads();

#pragma unroll
        for (int k = 0; k < 16; ++k) {
            float a[8], b[4];
#pragma unroll
            for (int i = 0; i < 8; ++i) a[i] = As[k][ty * 8 + i];
#pragma unroll
            for (int j = 0; j < 4; ++j) b[j] = Bs[k][tx * 4 + j];
#pragma unroll
            for (int i = 0; i < 8; ++i)
#pragma unroll
                for (int j = 0; j < 4; ++j) acc[i][j] += a[i] * b[j];
        }
        __syncthreads();
    }

#pragma unroll
    for (int i = 0; i < 8; ++i) {
        int s = m0 + ty * 8 + i;
#pragma unroll
        for (int j = 0; j < 4; ++j) {
            int n = n0 + tx * 4 + j;
            if (mode == 0)
                C[(size_t)s * 1024 + n] = acc[i][j];
            else
                C[((size_t)(n >> 6) * SEQ + s) * 64 + (n & 63)] = acc[i][j];
        }
    }
}

// ---------------------------------------------------------------------------
// Flash attention (fp32, causal). One CTA per (head, 64-row q block).
// 256 threads = 16x16, each computes a 4x4 sub-tile of the 64x64 score block.
// Online softmax; causal blocks beyond the diagonal are skipped entirely.
// Output written directly in z_flat layout [S, H*64].
// Dynamic smem: Qs/Ks (e-major, pad 65), Vs (kr-major, pad 65), Ps (kr-major).
// ---------------------------------------------------------------------------
#define FA_SMEM_FLOATS (4 * 64 * 65)
#define FA_SMEM_BYTES  (FA_SMEM_FLOATS * 4)

__global__ __launch_bounds__(256) void flash_kernel(
    const float* __restrict__ Q, const float* __restrict__ K,
    const float* __restrict__ V, float* __restrict__ Z)
{
    extern __shared__ float sm[];
    float* Qs = sm;                 // Qs[e*65 + qr]
    float* Ks = sm + 64 * 65;       // Ks[e*65 + kr]
    float* Vs = sm + 2 * 64 * 65;   // Vs[kr*65 + e]
    float* Ps = sm + 3 * 64 * 65;   // Ps[kr*65 + qr]

    const int tid = threadIdx.x;
    const int tx = tid & 15;        // key-col direction
    const int ty = tid >> 4;        // query-row direction
    const int h  = blockIdx.y;
    const int iq = gridDim.x - 1 - blockIdx.x;  // big work first

    const float* Qh = Q + ((size_t)h * SEQ + iq * 64) * 64;

    // Load Q tile transposed (e-major)
    for (int idx = tid; idx < 64 * 64; idx += 256) {
        int r = idx >> 6, e = idx & 63;
        Qs[e * 65 + r] = Qh[idx];
    }

    float m[4], l[4], O[4][4];
#pragma unroll
    for (int i = 0; i < 4; ++i) {
        m[i] = -1.0e30f; l[i] = 0.0f;
#pragma unroll
        for (int j = 0; j < 4; ++j) O[i][j] = 0.0f;
    }

    for (int jk = 0; jk <= iq; ++jk) {
        __syncthreads();   // protect Ks/Vs/Ps from previous iteration readers
        const float* Kh = K + ((size_t)h * SEQ + jk * 64) * 64;
        const float* Vh = V + ((size_t)h * SEQ + jk * 64) * 64;
        for (int idx = tid; idx < 64 * 64; idx += 256) {
            int r = idx >> 6, e = idx & 63;
            Ks[e * 65 + r] = Kh[idx];
            Vs[r * 65 + e] = Vh[idx];
        }
        __syncthreads();

        // S = scale * Q K^T  (4x4 per thread)
        float acc[4][4];
#pragma unroll
        for (int i = 0; i < 4; ++i)
#pragma unroll
            for (int j = 0; j < 4; ++j) acc[i][j] = 0.0f;

#pragma unroll 8
        for (int e = 0; e < 64; ++e) {
            float a[4], b[4];
#pragma unroll
            for (int i = 0; i < 4; ++i) a[i] = Qs[e * 65 + ty * 4 + i];
#pragma unroll
            for (int j = 0; j < 4; ++j) b[j] = Ks[e * 65 + tx * 4 + j];
#pragma unroll
            for (int i = 0; i < 4; ++i)
#pragma unroll
                for (int j = 0; j < 4; ++j) acc[i][j] += a[i] * b[j];
        }

#pragma unroll
        for (int i = 0; i < 4; ++i)
#pragma unroll
            for (int j = 0; j < 4; ++j) acc[i][j] *= 0.125f;  // 1/sqrt(64)

        if (jk == iq) {   // diagonal block: causal mask
#pragma unroll
            for (int i = 0; i < 4; ++i)
#pragma unroll
                for (int j = 0; j < 4; ++j)
                    if ((tx * 4 + j) > (ty * 4 + i)) acc[i][j] = -1.0e30f;
        }

        // Row max across the 16 tx lanes (shuffle within 16-lane group)
        float pm[4];
#pragma unroll
        for (int i = 0; i < 4; ++i)
            pm[i] = fmaxf(fmaxf(acc[i][0], acc[i][1]), fmaxf(acc[i][2], acc[i][3]));
#pragma unroll
        for (int off = 8; off >= 1; off >>= 1)
#pragma unroll
            for (int i = 0; i < 4; ++i)
                pm[i] = fmaxf(pm[i], __shfl_xor_sync(0xffffffffu, pm[i], off));

        float mn[4], al[4];
#pragma unroll
        for (int i = 0; i < 4; ++i) {
            mn[i] = fmaxf(m[i], pm[i]);
            al[i] = __expf(m[i] - mn[i]);
            m[i]  = mn[i];
        }

        float p[4][4], rs[4];
#pragma unroll
        for (int i = 0; i < 4; ++i) {
            rs[i] = 0.0f;
#pragma unroll
            for (int j = 0; j < 4; ++j) {
                p[i][j] = __expf(acc[i][j] - mn[i]);
                rs[i] += p[i][j];
            }
        }
#pragma unroll
        for (int off = 8; off >= 1; off >>= 1)
#pragma unroll
            for (int i = 0; i < 4; ++i)
                rs[i] += __shfl_xor_sync(0xffffffffu, rs[i], off);

#pragma unroll
        for (int i = 0; i < 4; ++i) {
            l[i] = l[i] * al[i] + rs[i];
#pragma unroll
            for (int j = 0; j < 4; ++j) O[i][j] *= al[i];
        }

        // Stage P to smem (kr-major) for the PV GEMM
#pragma unroll
        for (int i = 0; i < 4; ++i)
#pragma unroll
            for (int j = 0; j < 4; ++j)
                Ps[(tx * 4 + j) * 65 + (ty * 4 + i)] = p[i][j];
        __syncthreads();

        // O += P * V
#pragma unroll 8
        for (int kr = 0; kr < 64; ++kr) {
            float a[4], b[4];
#pragma unroll
            for (int i = 0; i < 4; ++i) a[i] = Ps[kr * 65 + ty * 4 + i];
#pragma unroll
            for (int j = 0; j < 4; ++j) b[j] = Vs[kr * 65 + tx * 4 + j];
#pragma unroll
            for (int i = 0; i < 4; ++i)
#pragma unroll
                for (int j = 0; j < 4; ++j) O[i][j] += a[i] * b[j];
        }
    }

    // Epilogue: normalize, write z_flat[s, h*64 + e]
#pragma unroll
    for (int i = 0; i < 4; ++i) {
        float inv = 1.0f / l[i];
        int s = iq * 64 + ty * 4 + i;
#pragma unroll
        for (int j = 0; j < 4; ++j)
            Z[(size_t)s * DMODEL + h * 64 + tx * 4 + j] = O[i][j] * inv;
    }
}

// ---------------------------------------------------------------------------
extern "C" void kernel_launch(void* const* d_in, const int* in_sizes, int n_in,
                              void* d_out, int out_size)
{
    const float* x   = (const float*)d_in[0];
    const float* W_K = (const float*)d_in[1];
    const float* W_Q = (const float*)d_in[2];
    const float* W_V = (const float*)d_in[3];
    const float* W_O = (const float*)d_in[4];
    float* out = (float*)d_out;

    float *q, *k, *v, *z;
    cudaGetSymbolAddress((void**)&q, g_q);
    cudaGetSymbolAddress((void**)&k, g_k);
    cudaGetSymbolAddress((void**)&v, g_v);
    cudaGetSymbolAddress((void**)&z, g_z);

    cudaFuncSetAttribute(flash_kernel,
                         cudaFuncAttributeMaxDynamicSharedMemorySize, FA_SMEM_BYTES);

    dim3 gg(SEQ / 128, DMODEL / 64);   // (32, 16)
    dim3 gb(256);

    // Q/K/V projections -> [H][S][64]
    sgemm_kernel<<<gg, gb>>>(x, W_Q, q, 1);
    sgemm_kernel<<<gg, gb>>>(x, W_K, k, 1);
    sgemm_kernel<<<gg, gb>>>(x, W_V, v, 1);

    // Causal flash attention -> z_flat [S, 1024]
    flash_kernel<<<dim3(SEQ / 64, NHEAD), gb, FA_SMEM_BYTES>>>(q, k, v, z);

    // Output projection -> out [S, 1024]
    sgemm_kernel<<<gg, gb>>>(z, W_O, out, 0);
}

// round 2
// speedup vs baseline: 1.0825x; 1.0825x over previous
#include <cuda_runtime.h>
#include <math.h>

#define SEQ    4096
#define DMODEL 1024
#define NHEAD  16
#define DHEAD  64

typedef unsigned long long u64;

// ---- packed fp32x2 helpers (Blackwell FFMA2 path) ----
__device__ __forceinline__ u64 ld2s(const float* p) { return *reinterpret_cast<const u64*>(p); }
__device__ __forceinline__ void st2s(float* p, u64 v) { *reinterpret_cast<u64*>(p) = v; }
__device__ __forceinline__ u64 fma2(u64 a, u64 b, u64 c) {
    u64 d; asm("fma.rn.f32x2 %0,%1,%2,%3;" : "=l"(d) : "l"(a), "l"(b), "l"(c)); return d;
}
__device__ __forceinline__ u64 mul2(u64 a, u64 b) {
    u64 d; asm("mul.rn.f32x2 %0,%1,%2;" : "=l"(d) : "l"(a), "l"(b)); return d;
}
__device__ __forceinline__ u64 pack2(float x, float y) {
    u64 r; asm("mov.b64 %0,{%1,%2};" : "=l"(r) : "f"(x), "f"(y)); return r;
}
__device__ __forceinline__ float hsum2(u64 v) {
    float x, y; asm("mov.b64 {%0,%1},%2;" : "=f"(x), "=f"(y) : "l"(v)); return x + y;
}

// Scratch (allocation-free: __device__ globals)
__device__ float g_q[(size_t)NHEAD * SEQ * DHEAD];
__device__ float g_k[(size_t)NHEAD * SEQ * DHEAD];
__device__ float g_v[(size_t)NHEAD * SEQ * DHEAD];
__device__ float g_z[(size_t)SEQ * DMODEL];

// ---------------------------------------------------------------------------
// SGEMM: C = A[4096,1024] * B[1024,1024]^T  via packed f32x2 along k.
// BM=128, BN=64, BK=32; 256 threads; TM=8, TN=4 per thread.
//   mode 0: C[s*1024 + n]
//   mode 1: C[((n>>6)*SEQ + s)*64 + (n&63)]   (per-head [H][S][64])
// ---------------------------------------------------------------------------
__global__ __launch_bounds__(256) void sgemm_kernel(
    const float* __restrict__ A, const float* __restrict__ B,
    float* __restrict__ C, int mode)
{
    __shared__ float As[128 * 32];   // natural [m][k], a-loads are broadcast
    __shared__ float Bs[64 * 32];    // [n][k2-xor-swizzled]

    const int tid = threadIdx.x;
    const int tx = tid & 15;         // n direction
    const int ty = tid >> 4;         // m direction
    const int m0 = blockIdx.x * 128;
    const int n0 = blockIdx.y * 64;

    u64 acc[8][4];
#pragma unroll
    for (int i = 0; i < 8; ++i)
#pragma unroll
        for (int j = 0; j < 4; ++j) acc[i][j] = 0ull;

    for (int k0 = 0; k0 < 1024; k0 += 32) {
        // A tile: 128x32, 1024 float4, natural layout
#pragma unroll
        for (int r = 0; r < 4; ++r) {
            int idx = tid + r * 256;
            int row = idx >> 3, c4 = idx & 7;
            float4 v = *(const float4*)(A + (size_t)(m0 + row) * 1024 + k0 + c4 * 4);
            *(float4*)(As + row * 32 + c4 * 4) = v;
        }
        // B tile: 64x32, xor-swizzled float2 columns: (n,k) -> n*32 + 2*((k>>1)^(n>>2)) + (k&1)
#pragma unroll
        for (int r = 0; r < 2; ++r) {
            int idx = tid + r * 256;
            int row = idx >> 3, c4 = idx & 7;
            float4 v = *(const float4*)(B + (size_t)(n0 + row) * 1024 + k0 + c4 * 4);
            int s = (row >> 2) & 15;
            st2s(Bs + row * 32 + (((c4 * 2)     ^ s) * 2), pack2(v.x, v.y));
            st2s(Bs + row * 32 + (((c4 * 2 + 1) ^ s) * 2), pack2(v.z, v.w));
        }
        __syncthreads();

#pragma unroll
        for (int k2 = 0; k2 < 16; ++k2) {
            u64 a2[8], b2[4];
#pragma unroll
            for (int i = 0; i < 8; ++i)
                a2[i] = ld2s(As + (ty * 8 + i) * 32 + k2 * 2);
#pragma unroll
            for (int j = 0; j < 4; ++j)
                b2[j] = ld2s(Bs + (tx * 4 + j) * 32 + ((k2 ^ tx) * 2));
#pragma unroll
            for (int i = 0; i < 8; ++i)
#pragma unroll
                for (int j = 0; j < 4; ++j)
                    acc[i][j] = fma2(a2[i], b2[j], acc[i][j]);
        }
        __syncthreads();
    }

#pragma unroll
    for (int i = 0; i < 8; ++i) {
        int sidx = m0 + ty * 8 + i;
#pragma unroll
        for (int j = 0; j < 4; ++j) {
            int n = n0 + tx * 4 + j;
            float c = hsum2(acc[i][j]);
            if (mode == 0)
                C[(size_t)sidx * 1024 + n] = c;
            else
                C[((size_t)(n >> 6) * SEQ + sidx) * 64 + (n & 63)] = c;
        }
    }
}

// ---------------------------------------------------------------------------
// Flash attention (fp32 via f32x2, causal). One CTA per (head, 64-row q block).
// 256 threads = 16x16, 4x4 sub-tile each. Contraction-packed FFMA2:
//   QK contracts over e  -> Q,K stored natural row-major (K xor-swizzled).
//   PV contracts over kr -> P stored q-major (kr-contiguous), V transpose-staged.
// ---------------------------------------------------------------------------
#define FA_SMEM_FLOATS (3 * 64 * 64 + 64 * 66)
#define FA_SMEM_BYTES  (FA_SMEM_FLOATS * 4)

__global__ __launch_bounds__(256) void flash_kernel(
    const float* __restrict__ Q, const float* __restrict__ K,
    const float* __restrict__ V, float* __restrict__ Z)
{
    extern __shared__ float sm[];
    float* Qs = sm;              // [q][e]   natural, stride 64
    float* Ks = sm + 4096;       // [kr][e]  xor-swizzled e2 cols, stride 64
    float* Vt = sm + 8192;       // [e][kr]  xor-swizzled kr2 cols, stride 64
    float* Ps = sm + 12288;      // [q][kr]  natural, stride 66

    const int tid = threadIdx.x;
    const int tx = tid & 15;     // key/e_out col direction
    const int ty = tid >> 4;     // query row direction
    const int h  = blockIdx.y;
    const int iq = gridDim.x - 1 - blockIdx.x;   // big work first

    const float* Qh = Q + ((size_t)h * SEQ + iq * 64) * 64;

    // Q tile: natural copy
#pragma unroll
    for (int r = 0; r < 4; ++r) {
        int idx = tid + r * 256;
        int row = idx >> 4, c4 = idx & 15;
        *(float4*)(Qs + row * 64 + c4 * 4) =
            *(const float4*)(Qh + row * 64 + c4 * 4);
    }

    float m[4], l[4];
    u64 O2[4][4];
#pragma unroll
    for (int i = 0; i < 4; ++i) {
        m[i] = -1.0e30f; l[i] = 0.0f;
#pragma unroll
        for (int j = 0; j < 4; ++j) O2[i][j] = 0ull;
    }

    for (int jk = 0; jk <= iq; ++jk) {
        __syncthreads();   // guards Q first iter; Ks/Vt/Ps reuse afterwards
        const float* Kh = K + ((size_t)h * SEQ + jk * 64) * 64;
        const float* Vh = V + ((size_t)h * SEQ + jk * 64) * 64;
#pragma unroll
        for (int r = 0; r < 4; ++r) {
            int idx = tid + r * 256;
            int row = idx >> 4, c4 = idx & 15;
            // K: natural rows, xor-swizzled float2 columns
            float4 kv = *(const float4*)(Kh + row * 64 + c4 * 4);
            int s = (row >> 2) & 15;
            st2s(Ks + row * 64 + (((c4 * 2)     ^ s) * 2), pack2(kv.x, kv.y));
            st2s(Ks + row * 64 + (((c4 * 2 + 1) ^ s) * 2), pack2(kv.z, kv.w));
            // V: transpose into [e][kr] with swizzled kr2: (e,kr) -> e*64 + 2*((kr>>1)^(e>>2)) + (kr&1)
            float4 vv = *(const float4*)(Vh + row * 64 + c4 * 4);
            int colp = ((row >> 1) ^ (c4 & 15)) * 2 + (row & 1);
            Vt[(c4 * 4 + 0) * 64 + colp] = vv.x;
            Vt[(c4 * 4 + 1) * 64 + colp] = vv.y;
            Vt[(c4 * 4 + 2) * 64 + colp] = vv.z;
            Vt[(c4 * 4 + 3) * 64 + colp] = vv.w;
        }
        __syncthreads();

        // --- S = scale * Q K^T, packed along e ---
        u64 acc2[4][4];
#pragma unroll
        for (int i = 0; i < 4; ++i)
#pragma unroll
            for (int j = 0; j < 4; ++j) acc2[i][j] = 0ull;

#pragma unroll 4
        for (int e2 = 0; e2 < 32; ++e2) {
            u64 a2[4], b2[4];
#pragma unroll
            for (int i = 0; i < 4; ++i)
                a2[i] = ld2s(Qs + (ty * 4 + i) * 64 + e2 * 2);
#pragma unroll
            for (int j = 0; j < 4; ++j)
                b2[j] = ld2s(Ks + (tx * 4 + j) * 64 + ((e2 ^ tx) * 2));
#pragma unroll
            for (int i = 0; i < 4; ++i)
#pragma unroll
                for (int j = 0; j < 4; ++j)
                    acc2[i][j] = fma2(a2[i], b2[j], acc2[i][j]);
        }

        float sc[4][4];
#pragma unroll
        for (int i = 0; i < 4; ++i)
#pragma unroll
            for (int j = 0; j < 4; ++j)
                sc[i][j] = hsum2(acc2[i][j]) * 0.125f;   // 1/sqrt(64)

        if (jk == iq) {   // diagonal block causal mask
#pragma unroll
            for (int i = 0; i < 4; ++i)
#pragma unroll
                for (int j = 0; j < 4; ++j)
                    if ((tx * 4 + j) > (ty * 4 + i)) sc[i][j] = -1.0e30f;
        }

        // row max over 16 tx lanes
        float pm[4];
#pragma unroll
        for (int i = 0; i < 4; ++i)
            pm[i] = fmaxf(fmaxf(sc[i][0], sc[i][1]), fmaxf(sc[i][2], sc[i][3]));
#pragma unroll
        for (int off = 8; off >= 1; off >>= 1)
#pragma unroll
            for (int i = 0; i < 4; ++i)
                pm[i] = fmaxf(pm[i], __shfl_xor_sync(0xffffffffu, pm[i], off));

        float al[4];
#pragma unroll
        for (int i = 0; i < 4; ++i) {
            float mn = fmaxf(m[i], pm[i]);
            al[i] = __expf(m[i] - mn);
            m[i] = mn;
        }

        float p[4][4], rs[4];
#pragma unroll
        for (int i = 0; i < 4; ++i) {
            rs[i] = 0.0f;
#pragma unroll
            for (int j = 0; j < 4; ++j) {
                p[i][j] = __expf(sc[i][j] - m[i]);
                rs[i] += p[i][j];
            }
        }
#pragma unroll
        for (int off = 8; off >= 1; off >>= 1)
#pragma unroll
            for (int i = 0; i < 4; ++i)
                rs[i] += __shfl_xor_sync(0xffffffffu, rs[i], off);

#pragma unroll
        for (int i = 0; i < 4; ++i) {
            l[i] = l[i] * al[i] + rs[i];
            u64 al2 = pack2(al[i], al[i]);
#pragma unroll
            for (int j = 0; j < 4; ++j) O2[i][j] = mul2(O2[i][j], al2);
        }

        // stage P q-major, kr-contiguous (pairs along kr)
#pragma unroll
        for (int i = 0; i < 4; ++i)
#pragma unroll
            for (int j2 = 0; j2 < 2; ++j2)
                st2s(Ps + (ty * 4 + i) * 66 + tx * 4 + j2 * 2,
                     pack2(p[i][2 * j2], p[i][2 * j2 + 1]));
        __syncthreads();

        // --- O += P V, packed along kr ---
#pragma unroll 4
        for (int kr2 = 0; kr2 < 32; ++kr2) {
            u64 a2[4], b2[4];
#pragma unroll
            for (int i = 0; i < 4; ++i)
                a2[i] = ld2s(Ps + (ty * 4 + i) * 66 + kr2 * 2);
#pragma unroll
            for (int j = 0; j < 4; ++j)
                b2[j] = ld2s(Vt + (tx * 4 + j) * 64 + ((kr2 ^ tx) * 2));
#pragma unroll
            for (int i = 0; i < 4; ++i)
#pragma unroll
                for (int j = 0; j < 4; ++j)
                    O2[i][j] = fma2(a2[i], b2[j], O2[i][j]);
        }
    }

    // epilogue: collapse pairs, normalize, write z_flat[s, h*64+e]
#pragma unroll
    for (int i = 0; i < 4; ++i) {
        float inv = 1.0f / l[i];
        int s = iq * 64 + ty * 4 + i;
#pragma unroll
        for (int j = 0; j < 4; ++j)
            Z[(size_t)s * DMODEL + h * 64 + tx * 4 + j] = hsum2(O2[i][j]) * inv;
    }
}

// ---------------------------------------------------------------------------
extern "C" void kernel_launch(void* const* d_in, const int* in_sizes, int n_in,
                              void* d_out, int out_size)
{
    const float* x   = (const float*)d_in[0];
    const float* W_K = (const float*)d_in[1];
    const float* W_Q = (const float*)d_in[2];
    const float* W_V = (const float*)d_in[3];
    const float* W_O = (const float*)d_in[4];
    float* out = (float*)d_out;

    float *q, *k, *v, *z;
    cudaGetSymbolAddress((void**)&q, g_q);
    cudaGetSymbolAddress((void**)&k, g_k);
    cudaGetSymbolAddress((void**)&v, g_v);
    cudaGetSymbolAddress((void**)&z, g_z);

    cudaFuncSetAttribute(flash_kernel,
                         cudaFuncAttributeMaxDynamicSharedMemorySize, FA_SMEM_BYTES);

    dim3 gg(SEQ / 128, DMODEL / 64);   // (32, 16)
    dim3 gb(256);

    sgemm_kernel<<<gg, gb>>>(x, W_Q, q, 1);
    sgemm_kernel<<<gg, gb>>>(x, W_K, k, 1);
    sgemm_kernel<<<gg, gb>>>(x, W_V, v, 1);

    flash_kernel<<<dim3(SEQ / 64, NHEAD), gb, FA_SMEM_BYTES>>>(q, k, v, z);

    sgemm_kernel<<<gg, gb>>>(z, W_O, out, 0);
}

// round 4
// speedup vs baseline: 1.5582x; 1.4394x over previous
#include <cuda_runtime.h>
#include <cuda_bf16.h>
#include <cstdint>
#include <math.h>

#define SEQ    4096
#define DMODEL 1024
#define NHEAD  16
#define DHEAD  64

typedef unsigned long long u64;

// ---- packed fp32x2 helpers (flash kernel) ----
__device__ __forceinline__ u64 ld2s(const float* p) { return *reinterpret_cast<const u64*>(p); }
__device__ __forceinline__ void st2s(float* p, u64 v) { *reinterpret_cast<u64*>(p) = v; }
__device__ __forceinline__ u64 fma2(u64 a, u64 b, u64 c) {
    u64 d; asm("fma.rn.f32x2 %0,%1,%2,%3;" : "=l"(d) : "l"(a), "l"(b), "l"(c)); return d;
}
__device__ __forceinline__ u64 mul2(u64 a, u64 b) {
    u64 d; asm("mul.rn.f32x2 %0,%1,%2;" : "=l"(d) : "l"(a), "l"(b)); return d;
}
__device__ __forceinline__ u64 pack2(float x, float y) {
    u64 r; asm("mov.b64 %0,{%1,%2};" : "=l"(r) : "f"(x), "f"(y)); return r;
}
__device__ __forceinline__ float hsum2(u64 v) {
    float x, y; asm("mov.b64 {%0,%1},%2;" : "=f"(x), "=f"(y) : "l"(v)); return x + y;
}

__device__ __forceinline__ uint32_t smem_u32(const void* p) {
    uint32_t a;
    asm("{ .reg .u64 t; cvta.to.shared.u64 t, %1; cvt.u32.u64 %0, t; }" : "=r"(a) : "l"(p));
    return a;
}
__device__ __forceinline__ void ldsm_x4(uint32_t* r, uint32_t addr) {
    asm volatile("ldmatrix.sync.aligned.m8n8.x4.shared.b16 {%0,%1,%2,%3}, [%4];"
        : "=r"(r[0]), "=r"(r[1]), "=r"(r[2]), "=r"(r[3]) : "r"(addr));
}
__device__ __forceinline__ void mma_bf16(float* c, const uint32_t* a, const uint32_t* b) {
    asm volatile(
        "mma.sync.aligned.m16n8k16.row.col.f32.bf16.bf16.f32 "
        "{%0,%1,%2,%3}, {%4,%5,%6,%7}, {%8,%9}, {%0,%1,%2,%3};"
        : "+f"(c[0]), "+f"(c[1]), "+f"(c[2]), "+f"(c[3])
        : "r"(a[0]), "r"(a[1]), "r"(a[2]), "r"(a[3]), "r"(b[0]), "r"(b[1]));
}

// ========================= scratch (__device__ globals) =====================
__device__ float g_q[(size_t)NHEAD * SEQ * DHEAD];
__device__ float g_k[(size_t)NHEAD * SEQ * DHEAD];
__device__ float g_v[(size_t)NHEAD * SEQ * DHEAD];
__device__ float g_z[(size_t)SEQ * DMODEL];
__device__ __nv_bfloat16 g_xh[(size_t)SEQ * DMODEL], g_xl[(size_t)SEQ * DMODEL];
__device__ __nv_bfloat16 g_zh[(size_t)SEQ * DMODEL], g_zl[(size_t)SEQ * DMODEL];
__device__ __nv_bfloat16 g_wqh[DMODEL * DMODEL], g_wql[DMODEL * DMODEL];
__device__ __nv_bfloat16 g_wkh[DMODEL * DMODEL], g_wkl[DMODEL * DMODEL];
__device__ __nv_bfloat16 g_wvh[DMODEL * DMODEL], g_wvl[DMODEL * DMODEL];
__device__ __nv_bfloat16 g_woh[DMODEL * DMODEL], g_wol[DMODEL * DMODEL];

// ============================ split kernel ==================================
__global__ __launch_bounds__(256) void split_kernel(
    const float* __restrict__ in, __nv_bfloat16* __restrict__ hi,
    __nv_bfloat16* __restrict__ lo, int n4)
{
    int i = blockIdx.x * 256 + threadIdx.x;
    if (i >= n4) return;
    float4 v = ((const float4*)in)[i];
    __nv_bfloat16 h0 = __float2bfloat16(v.x), h1 = __float2bfloat16(v.y);
    __nv_bfloat16 h2 = __float2bfloat16(v.z), h3 = __float2bfloat16(v.w);
    __nv_bfloat162* H = (__nv_bfloat162*)hi;
    __nv_bfloat162* L = (__nv_bfloat162*)lo;
    H[2 * i]     = __nv_bfloat162(h0, h1);
    H[2 * i + 1] = __nv_bfloat162(h2, h3);
    L[2 * i]     = __nv_bfloat162(__float2bfloat16(v.x - __bfloat162float(h0)),
                                  __float2bfloat16(v.y - __bfloat162float(h1)));
    L[2 * i + 1] = __nv_bfloat162(__float2bfloat16(v.z - __bfloat162float(h2)),
                                  __float2bfloat16(v.w - __bfloat162float(h3)));
}

// ================= mma.sync bf16 GEMM (3-term split) ========================
// C[4096,1024] = A * B^T  as  Ah*Bh + Ah*Bl + Al*Bh  (bf16 -> f32 accum)
// CTA tile 128x128, BK=32, 8 warps (warp tile 32m x 64n).
//   mode 0: C[s*1024 + n]
//   mode 1: C[((n>>6)*SEQ + s)*64 + (n&63)]   ([H][S][64])
// Smem: padded stride 40 bf16 (80B): 16B-aligned rows, ldmatrix conflict-free.
// ---------------------------------------------------------------------------
#define GSTR 40

__global__ __launch_bounds__(256) void gemm_mma(
    const __nv_bfloat16* __restrict__ Ah, const __nv_bfloat16* __restrict__ Al,
    const __nv_bfloat16* __restrict__ Bh, const __nv_bfloat16* __restrict__ Bl,
    float* __restrict__ C, int mode)
{
    __shared__ __nv_bfloat16 As[128 * GSTR];
    __shared__ __nv_bfloat16 Bs[128 * GSTR];

    const int tid  = threadIdx.x;
    const int warp = tid >> 5, lane = tid & 31;
    const int wm = (warp & 3) * 32;      // warp m-offset in tile
    const int wn = (warp >> 2) * 64;     // warp n-offset in tile
    const int m0 = blockIdx.x * 128;
    const int n0 = blockIdx.y * 128;

    // ldmatrix source addresses (byte, shared-space)
    const uint32_t as_base = smem_u32(As);
    const uint32_t bs_base = smem_u32(Bs);
    // A x4: lanes 0-15 -> rows (lane%16), col 0; lanes 16-31 -> rows, col 8
    const uint32_t a_addr0 = as_base +
        ((wm + (lane & 15)) * GSTR + (lane >> 4) * 8) * 2;
    // B x4: lanes 0-7 n rows col0; 8-15 n rows col8; 16-23 n+8 col0; 24-31 n+8 col8
    const uint32_t b_addr0 = bs_base +
        ((wn + (lane & 7) + ((lane >> 4) * 8)) * GSTR + (((lane >> 3) & 1) * 8)) * 2;

    float acc[2][8][4];
#pragma unroll
    for (int i = 0; i < 2; ++i)
#pragma unroll
        for (int j = 0; j < 8; ++j)
#pragma unroll
            for (int t = 0; t < 4; ++t) acc[i][j][t] = 0.0f;

#pragma unroll 1
    for (int sp = 0; sp < 3; ++sp) {
        const __nv_bfloat16* Ap = (sp == 2) ? Al : Ah;
        const __nv_bfloat16* Bp = (sp == 1) ? Bl : Bh;
#pragma unroll 1
        for (int k0 = 0; k0 < DMODEL; k0 += 32) {
            // Load 128x32 bf16 tiles of A and B (2 uint4 each per thread)
#pragma unroll
            for (int it = 0; it < 2; ++it) {
                int idx = tid + it * 256;
                int row = idx >> 2, c4 = idx & 3;
                *(uint4*)(As + row * GSTR + c4 * 8) =
                    *(const uint4*)(Ap + (size_t)(m0 + row) * DMODEL + k0 + c4 * 8);
                *(uint4*)(Bs + row * GSTR + c4 * 8) =
                    *(const uint4*)(Bp + (size_t)(n0 + row) * DMODEL + k0 + c4 * 8);
            }
            __syncthreads();

#pragma unroll
            for (int kk = 0; kk < 2; ++kk) {
                uint32_t a[2][4], b[8][2];
#pragma unroll
                for (int mt = 0; mt < 2; ++mt)
                    ldsm_x4(a[mt], a_addr0 + (mt * 16 * GSTR + kk * 16) * 2);
#pragma unroll
                for (int j = 0; j < 4; ++j) {
                    uint32_t r[4];
                    ldsm_x4(r, b_addr0 + (j * 16 * GSTR + kk * 16) * 2);
                    b[j * 2][0] = r[0]; b[j * 2][1] = r[1];
                    b[j * 2 + 1][0] = r[2]; b[j * 2 + 1][1] = r[3];
                }
#pragma unroll
                for (int mt = 0; mt < 2; ++mt)
#pragma unroll
                    for (int nt = 0; nt < 8; ++nt)
                        mma_bf16(acc[mt][nt], a[mt], b[nt]);
            }
            __syncthreads();
        }
    }

    // Epilogue: c0,c1 at (m, n..n+1); c2,c3 at (m+8, n..n+1)
#pragma unroll
    for (int mt = 0; mt < 2; ++mt) {
#pragma unroll
        for (int nt = 0; nt < 8; ++nt) {
            int m = m0 + wm + mt * 16 + (lane >> 2);
            int n = n0 + wn + nt * 8 + 2 * (lane & 3);
            if (mode == 0) {
                *(float2*)(C + (size_t)m * DMODEL + n) =
                    make_float2(acc[mt][nt][0], acc[mt][nt][1]);
                *(float2*)(C + (size_t)(m + 8) * DMODEL + n) =
                    make_float2(acc[mt][nt][2], acc[mt][nt][3]);
            } else {
                size_t base = ((size_t)(n >> 6) * SEQ + m) * 64 + (n & 63);
                *(float2*)(C + base) = make_float2(acc[mt][nt][0], acc[mt][nt][1]);
                *(float2*)(C + base + 8 * 64) = make_float2(acc[mt][nt][2], acc[mt][nt][3]);
            }
        }
    }
}

// ====================== flash attention (f32x2 SIMT) ========================
#define FA_SMEM_FLOATS (3 * 64 * 64 + 64 * 66)
#define FA_SMEM_BYTES  (FA_SMEM_FLOATS * 4)

__global__ __launch_bounds__(256) void flash_kernel(
    const float* __restrict__ Q, const float* __restrict__ K,
    const float* __restrict__ V, float* __restrict__ Z)
{
    extern __shared__ float sm[];
    float* Qs = sm;              // [q][e]   natural, stride 64
    float* Ks = sm + 4096;       // [kr][e]  xor-swizzled e2 cols
    float* Vt = sm + 8192;       // [e][kr]  xor-swizzled kr2 cols
    float* Ps = sm + 12288;      // [q][kr]  natural, stride 66

    const int tid = threadIdx.x;
    const int tx = tid & 15;
    const int ty = tid >> 4;
    const int h  = blockIdx.y;
    const int iq = gridDim.x - 1 - blockIdx.x;

    const float* Qh = Q + ((size_t)h * SEQ + iq * 64) * 64;
#pragma unroll
    for (int r = 0; r < 4; ++r) {
        int idx = tid + r * 256;
        int row = idx >> 4, c4 = idx & 15;
        *(float4*)(Qs + row * 64 + c4 * 4) = *(const float4*)(Qh + row * 64 + c4 * 4);
    }

    float m[4], l[4];
    u64 O2[4][4];
#pragma unroll
    for (int i = 0; i < 4; ++i) {
        m[i] = -1.0e30f; l[i] = 0.0f;
#pragma unroll
        for (int j = 0; j < 4; ++j) O2[i][j] = 0ull;
    }

    for (int jk = 0; jk <= iq; ++jk) {
        __syncthreads();
        const float* Kh = K + ((size_t)h * SEQ + jk * 64) * 64;
        const float* Vh = V + ((size_t)h * SEQ + jk * 64) * 64;
#pragma unroll
        for (int r = 0; r < 4; ++r) {
            int idx = tid + r * 256;
            int row = idx >> 4, c4 = idx & 15;
            float4 kv = *(const float4*)(Kh + row * 64 + c4 * 4);
            int s = (row >> 2) & 15;
            st2s(Ks + row * 64 + (((c4 * 2)     ^ s) * 2), pack2(kv.x, kv.y));
            st2s(Ks + row * 64 + (((c4 * 2 + 1) ^ s) * 2), pack2(kv.z, kv.w));
            float4 vv = *(const float4*)(Vh + row * 64 + c4 * 4);
            int colp = ((row >> 1) ^ (c4 & 15)) * 2 + (row & 1);
            Vt[(c4 * 4 + 0) * 64 + colp] = vv.x;
            Vt[(c4 * 4 + 1) * 64 + colp] = vv.y;
            Vt[(c4 * 4 + 2) * 64 + colp] = vv.z;
            Vt[(c4 * 4 + 3) * 64 + colp] = vv.w;
        }
        __syncthreads();

        u64 acc2[4][4];
#pragma unroll
        for (int i = 0; i < 4; ++i)
#pragma unroll
            for (int j = 0; j < 4; ++j) acc2[i][j] = 0ull;

#pragma unroll 4
        for (int e2 = 0; e2 < 32; ++e2) {
            u64 a2[4], b2[4];
#pragma unroll
            for (int i = 0; i < 4; ++i) a2[i] = ld2s(Qs + (ty * 4 + i) * 64 + e2 * 2);
#pragma unroll
            for (int j = 0; j < 4; ++j) b2[j] = ld2s(Ks + (tx * 4 + j) * 64 + ((e2 ^ tx) * 2));
#pragma unroll
            for (int i = 0; i < 4; ++i)
#pragma unroll
                for (int j = 0; j < 4; ++j) acc2[i][j] = fma2(a2[i], b2[j], acc2[i][j]);
        }

        float sc[4][4];
#pragma unroll
        for (int i = 0; i < 4; ++i)
#pragma unroll
            for (int j = 0; j < 4; ++j) sc[i][j] = hsum2(acc2[i][j]) * 0.125f;

        if (jk == iq) {
#pragma unroll
            for (int i = 0; i < 4; ++i)
#pragma unroll
                for (int j = 0; j < 4; ++j)
                    if ((tx * 4 + j) > (ty * 4 + i)) sc[i][j] = -1.0e30f;
        }

        float pm[4];
#pragma unroll
        for (int i = 0; i < 4; ++i)
            pm[i] = fmaxf(fmaxf(sc[i][0], sc[i][1]), fmaxf(sc[i][2], sc[i][3]));
#pragma unroll
        for (int off = 8; off >= 1; off >>= 1)
#pragma unroll
            for (int i = 0; i < 4; ++i)
                pm[i] = fmaxf(pm[i], __shfl_xor_sync(0xffffffffu, pm[i], off));

        float al[4];
#pragma unroll
        for (int i = 0; i < 4; ++i) {
            float mn = fmaxf(m[i], pm[i]);
            al[i] = __expf(m[i] - mn);
            m[i] = mn;
        }

        float p[4][4], rs[4];
#pragma unroll
        for (int i = 0; i < 4; ++i) {
            rs[i] = 0.0f;
#pragma unroll
            for (int j = 0; j < 4; ++j) {
                p[i][j] = __expf(sc[i][j] - m[i]);
                rs[i] += p[i][j];
            }
        }
#pragma unroll
        for (int off = 8; off >= 1; off >>= 1)
#pragma unroll
            for (int i = 0; i < 4; ++i)
                rs[i] += __shfl_xor_sync(0xffffffffu, rs[i], off);

#pragma unroll
        for (int i = 0; i < 4; ++i) {
            l[i] = l[i] * al[i] + rs[i];
            u64 al2 = pack2(al[i], al[i]);
#pragma unroll
            for (int j = 0; j < 4; ++j) O2[i][j] = mul2(O2[i][j], al2);
        }

#pragma unroll
        for (int i = 0; i < 4; ++i)
#pragma unroll
            for (int j2 = 0; j2 < 2; ++j2)
                st2s(Ps + (ty * 4 + i) * 66 + tx * 4 + j2 * 2,
                     pack2(p[i][2 * j2], p[i][2 * j2 + 1]));
        __syncthreads();

#pragma unroll 4
        for (int kr2 = 0; kr2 < 32; ++kr2) {
            u64 a2[4], b2[4];
#pragma unroll
            for (int i = 0; i < 4; ++i) a2[i] = ld2s(Ps + (ty * 4 + i) * 66 + kr2 * 2);
#pragma unroll
            for (int j = 0; j < 4; ++j) b2[j] = ld2s(Vt + (tx * 4 + j) * 64 + ((kr2 ^ tx) * 2));
#pragma unroll
            for (int i = 0; i < 4; ++i)
#pragma unroll
                for (int j = 0; j < 4; ++j) O2[i][j] = fma2(a2[i], b2[j], O2[i][j]);
        }
    }

#pragma unroll
    for (int i = 0; i < 4; ++i) {
        float inv = 1.0f / l[i];
        int s = iq * 64 + ty * 4 + i;
#pragma unroll
        for (int j = 0; j < 4; ++j)
            Z[(size_t)s * DMODEL + h * 64 + tx * 4 + j] = hsum2(O2[i][j]) * inv;
    }
}

// ---------------------------------------------------------------------------
extern "C" void kernel_launch(void* const* d_in, const int* in_sizes, int n_in,
                              void* d_out, int out_size)
{
    const float* x   = (const float*)d_in[0];
    const float* W_K = (const float*)d_in[1];
    const float* W_Q = (const float*)d_in[2];
    const float* W_V = (const float*)d_in[3];
    const float* W_O = (const float*)d_in[4];
    float* out = (float*)d_out;

    float *q, *k, *v, *z;
    cudaGetSymbolAddress((void**)&q, g_q);
    cudaGetSymbolAddress((void**)&k, g_k);
    cudaGetSymbolAddress((void**)&v, g_v);
    cudaGetSymbolAddress((void**)&z, g_z);
    __nv_bfloat16 *xh, *xl, *zh, *zl, *wqh, *wql, *wkh, *wkl, *wvh, *wvl, *woh, *wol;
    cudaGetSymbolAddress((void**)&xh, g_xh);   cudaGetSymbolAddress((void**)&xl, g_xl);
    cudaGetSymbolAddress((void**)&zh, g_zh);   cudaGetSymbolAddress((void**)&zl, g_zl);
    cudaGetSymbolAddress((void**)&wqh, g_wqh); cudaGetSymbolAddress((void**)&wql, g_wql);
    cudaGetSymbolAddress((void**)&wkh, g_wkh); cudaGetSymbolAddress((void**)&wkl, g_wkl);
    cudaGetSymbolAddress((void**)&wvh, g_wvh); cudaGetSymbolAddress((void**)&wvl, g_wvl);
    cudaGetSymbolAddress((void**)&woh, g_woh); cudaGetSymbolAddress((void**)&wol, g_wol);

    cudaFuncSetAttribute(flash_kernel,
                         cudaFuncAttributeMaxDynamicSharedMemorySize, FA_SMEM_BYTES);

    const int NX4 = SEQ * DMODEL / 4;      // 1048576
    const int NW4 = DMODEL * DMODEL / 4;   // 262144

    split_kernel<<<NX4 / 256, 256>>>(x, xh, xl, NX4);
    split_kernel<<<NW4 / 256, 256>>>(W_Q, wqh, wql, NW4);
    split_kernel<<<NW4 / 256, 256>>>(W_K, wkh, wkl, NW4);
    split_kernel<<<NW4 / 256, 256>>>(W_V, wvh, wvl, NW4);
    split_kernel<<<NW4 / 256, 256>>>(W_O, woh, wol, NW4);

    dim3 gg(SEQ / 128, DMODEL / 128);  // (32, 8)
    gemm_mma<<<gg, 256>>>(xh, xl, wqh, wql, q, 1);
    gemm_mma<<<gg, 256>>>(xh, xl, wkh, wkl, k, 1);
    gemm_mma<<<gg, 256>>>(xh, xl, wvh, wvl, v, 1);

    flash_kernel<<<dim3(SEQ / 64, NHEAD), 256, FA_SMEM_BYTES>>>(q, k, v, z);

    split_kernel<<<NX4 / 256, 256>>>(z, zh, zl, NX4);
    gemm_mma<<<gg, 256>>>(zh, zl, woh, wol, out, 0);
}

// round 6
// speedup vs baseline: 1.6041x; 1.0295x over previous
#include <cuda_runtime.h>
#include <cuda_bf16.h>
#include <cstdint>
#include <math.h>

#define SEQ    4096
#define DMODEL 1024
#define NHEAD  16
#define DHEAD  64

typedef unsigned long long u64;

// ---- packed fp32x2 helpers ----
__device__ __forceinline__ u64 ld2s(const float* p) { return *reinterpret_cast<const u64*>(p); }
__device__ __forceinline__ void st2s(float* p, u64 v) { *reinterpret_cast<u64*>(p) = v; }
__device__ __forceinline__ u64 fma2(u64 a, u64 b, u64 c) {
    u64 d; asm("fma.rn.f32x2 %0,%1,%2,%3;" : "=l"(d) : "l"(a), "l"(b), "l"(c)); return d;
}
__device__ __forceinline__ u64 mul2(u64 a, u64 b) {
    u64 d; asm("mul.rn.f32x2 %0,%1,%2;" : "=l"(d) : "l"(a), "l"(b)); return d;
}
__device__ __forceinline__ u64 pack2(float x, float y) {
    u64 r; asm("mov.b64 %0,{%1,%2};" : "=l"(r) : "f"(x), "f"(y)); return r;
}
__device__ __forceinline__ float hsum2(u64 v) {
    float x, y; asm("mov.b64 {%0,%1},%2;" : "=f"(x), "=f"(y) : "l"(v)); return x + y;
}

__device__ __forceinline__ uint32_t smem_u32(const void* p) {
    uint32_t a;
    asm("{ .reg .u64 t; cvta.to.shared.u64 t, %1; cvt.u32.u64 %0, t; }" : "=r"(a) : "l"(p));
    return a;
}
__device__ __forceinline__ void ldsm_x4(uint32_t* r, uint32_t addr) {
    asm volatile("ldmatrix.sync.aligned.m8n8.x4.shared.b16 {%0,%1,%2,%3}, [%4];"
        : "=r"(r[0]), "=r"(r[1]), "=r"(r[2]), "=r"(r[3]) : "r"(addr));
}
__device__ __forceinline__ void mma_bf16(float* c, const uint32_t* a, const uint32_t* b) {
    asm volatile(
        "mma.sync.aligned.m16n8k16.row.col.f32.bf16.bf16.f32 "
        "{%0,%1,%2,%3}, {%4,%5,%6,%7}, {%8,%9}, {%0,%1,%2,%3};"
        : "+f"(c[0]), "+f"(c[1]), "+f"(c[2]), "+f"(c[3])
        : "r"(a[0]), "r"(a[1]), "r"(a[2]), "r"(a[3]), "r"(b[0]), "r"(b[1]));
}

// ---- fast exp2 helpers ----
__device__ __forceinline__ float ex2f(float x) {
    float y; asm("ex2.approx.f32 %0,%1;" : "=f"(y) : "f"(x)); return y;
}
// two exp2 via one MUFU op (f16x2)
__device__ __forceinline__ void exp2_pair(float t0, float t1, float& p0, float& p1) {
    uint32_t h, e;
    asm("cvt.rn.f16x2.f32 %0,%1,%2;" : "=r"(h) : "f"(t1), "f"(t0));   // lo=t0, hi=t1
    asm("ex2.approx.f16x2 %0,%1;" : "=r"(e) : "r"(h));
    asm("{.reg .b16 lo,hi; mov.b32 {lo,hi},%2; cvt.f32.f16 %0,lo; cvt.f32.f16 %1,hi;}"
        : "=f"(p0), "=f"(p1) : "r"(e));
}

// ---- cp.async ----
#define CP_ASYNC16(dst, src) \
    asm volatile("cp.async.cg.shared.global [%0],[%1],16;" :: "r"(dst), "l"(src))
#define CP_COMMIT()  asm volatile("cp.async.commit_group;")
#define CP_WAIT(n)   asm volatile("cp.async.wait_group %0;" :: "n"(n))

// ========================= scratch (__device__ globals) =====================
__device__ float g_q[(size_t)NHEAD * SEQ * DHEAD];
__device__ float g_k[(size_t)NHEAD * SEQ * DHEAD];
__device__ float g_v[(size_t)NHEAD * SEQ * DHEAD];
__device__ float g_z[(size_t)SEQ * DMODEL];
__device__ __nv_bfloat16 g_xh[(size_t)SEQ * DMODEL], g_xl[(size_t)SEQ * DMODEL];
__device__ __nv_bfloat16 g_zh[(size_t)SEQ * DMODEL], g_zl[(size_t)SEQ * DMODEL];
__device__ __nv_bfloat16 g_wqh[DMODEL * DMODEL], g_wql[DMODEL * DMODEL];
__device__ __nv_bfloat16 g_wkh[DMODEL * DMODEL], g_wkl[DMODEL * DMODEL];
__device__ __nv_bfloat16 g_wvh[DMODEL * DMODEL], g_wvl[DMODEL * DMODEL];
__device__ __nv_bfloat16 g_woh[DMODEL * DMODEL], g_wol[DMODEL * DMODEL];

// ============================ split kernel ==================================
__global__ __launch_bounds__(256) void split_kernel(
    const float* __restrict__ in, __nv_bfloat16* __restrict__ hi,
    __nv_bfloat16* __restrict__ lo, int n4)
{
    int i = blockIdx.x * 256 + threadIdx.x;
    if (i >= n4) return;
    float4 v = ((const float4*)in)[i];
    __nv_bfloat16 h0 = __float2bfloat16(v.x), h1 = __float2bfloat16(v.y);
    __nv_bfloat16 h2 = __float2bfloat16(v.z), h3 = __float2bfloat16(v.w);
    __nv_bfloat162* H = (__nv_bfloat162*)hi;
    __nv_bfloat162* L = (__nv_bfloat162*)lo;
    H[2 * i]     = __nv_bfloat162(h0, h1);
    H[2 * i + 1] = __nv_bfloat162(h2, h3);
    L[2 * i]     = __nv_bfloat162(__float2bfloat16(v.x - __bfloat162float(h0)),
                                  __float2bfloat16(v.y - __bfloat162float(h1)));
    L[2 * i + 1] = __nv_bfloat162(__float2bfloat16(v.z - __bfloat162float(h2)),
                                  __float2bfloat16(v.w - __bfloat162float(h3)));
}

// ================= mma.sync bf16 GEMM (3-term split, cp.async 2-stage) ======
#define GSTR 40
#define GBUF (128 * GSTR)          // bf16 elements per tile buffer
#define NITER 96                    // 3 split terms x 32 K-chunks

__global__ __launch_bounds__(256) void gemm_mma(
    const __nv_bfloat16* __restrict__ Ah, const __nv_bfloat16* __restrict__ Al,
    const __nv_bfloat16* __restrict__ Bh, const __nv_bfloat16* __restrict__ Bl,
    float* __restrict__ C, int mode)
{
    __shared__ __nv_bfloat16 As[2][GBUF];
    __shared__ __nv_bfloat16 Bs[2][GBUF];

    const int tid  = threadIdx.x;
    const int warp = tid >> 5, lane = tid & 31;
    const int wm = (warp & 3) * 32;
    const int wn = (warp >> 2) * 64;
    const int m0 = blockIdx.x * 128;
    const int n0 = blockIdx.y * 128;

    const uint32_t as_base = smem_u32(As);
    const uint32_t bs_base = smem_u32(Bs);
    const uint32_t a_addr0 = as_base + ((wm + (lane & 15)) * GSTR + (lane >> 4) * 8) * 2;
    const uint32_t b_addr0 = bs_base +
        ((wn + (lane & 7) + ((lane >> 4) * 8)) * GSTR + (((lane >> 3) & 1) * 8)) * 2;

    // per-thread copy slots: 2 x 16B for A, 2 x 16B for B
    const int crow0 = tid >> 2,        ccol = (tid & 3) * 8;
    const int crow1 = (tid + 256) >> 2;

    const __nv_bfloat16* Aps[3]; const __nv_bfloat16* Bps[3];
    Aps[0] = Ah; Bps[0] = Bh;  Aps[1] = Ah; Bps[1] = Bl;  Aps[2] = Al; Bps[2] = Bh;

    float acc[2][8][4];
#pragma unroll
    for (int i = 0; i < 2; ++i)
#pragma unroll
        for (int j = 0; j < 8; ++j)
#pragma unroll
            for (int t = 0; t < 4; ++t) acc[i][j][t] = 0.0f;

    // issue stage 0
    {
        const __nv_bfloat16* Ap = Aps[0]; const __nv_bfloat16* Bp = Bps[0];
        CP_ASYNC16(as_base + (crow0 * GSTR + ccol) * 2, Ap + (size_t)(m0 + crow0) * DMODEL + ccol);
        CP_ASYNC16(as_base + (crow1 * GSTR + ccol) * 2, Ap + (size_t)(m0 + crow1) * DMODEL + ccol);
        CP_ASYNC16(bs_base + (crow0 * GSTR + ccol) * 2, Bp + (size_t)(n0 + crow0) * DMODEL + ccol);
        CP_ASYNC16(bs_base + (crow1 * GSTR + ccol) * 2, Bp + (size_t)(n0 + crow1) * DMODEL + ccol);
        CP_COMMIT();
    }

#pragma unroll 1
    for (int c = 0; c < NITER; ++c) {
        const int buf = c & 1;
        if (c + 1 < NITER) {
            const int cn = c + 1;
            const __nv_bfloat16* Ap = Aps[cn >> 5];
            const __nv_bfloat16* Bp = Bps[cn >> 5];
            const int k0 = (cn & 31) * 32;
            const uint32_t ao = as_base + (cn & 1) * GBUF * 2;
            const uint32_t bo = bs_base + (cn & 1) * GBUF * 2;
            CP_ASYNC16(ao + (crow0 * GSTR + ccol) * 2, Ap + (size_t)(m0 + crow0) * DMODEL + k0 + ccol);
            CP_ASYNC16(ao + (crow1 * GSTR + ccol) * 2, Ap + (size_t)(m0 + crow1) * DMODEL + k0 + ccol);
            CP_ASYNC16(bo + (crow0 * GSTR + ccol) * 2, Bp + (size_t)(n0 + crow0) * DMODEL + k0 + ccol);
            CP_ASYNC16(bo + (crow1 * GSTR + ccol) * 2, Bp + (size_t)(n0 + crow1) * DMODEL + k0 + ccol);
            CP_COMMIT();
            CP_WAIT(1);
        } else {
            CP_WAIT(0);
        }
        __syncthreads();

        const uint32_t abuf = buf * GBUF * 2;
#pragma unroll
        for (int kk = 0; kk < 2; ++kk) {
            uint32_t a[2][4], b[8][2];
#pragma unroll
            for (int mt = 0; mt < 2; ++mt)
                ldsm_x4(a[mt], a_addr0 + abuf + (mt * 16 * GSTR + kk * 16) * 2);
#pragma unroll
            for (int j = 0; j < 4; ++j) {
                uint32_t r[4];
                ldsm_x4(r, b_addr0 + abuf + (j * 16 * GSTR + kk * 16) * 2);
                b[j * 2][0] = r[0]; b[j * 2][1] = r[1];
                b[j * 2 + 1][0] = r[2]; b[j * 2 + 1][1] = r[3];
            }
#pragma unroll
            for (int mt = 0; mt < 2; ++mt)
#pragma unroll
                for (int nt = 0; nt < 8; ++nt)
                    mma_bf16(acc[mt][nt], a[mt], b[nt]);
        }
        __syncthreads();   // protect buf before re-fill at c+2
    }

#pragma unroll
    for (int mt = 0; mt < 2; ++mt) {
#pragma unroll
        for (int nt = 0; nt < 8; ++nt) {
            int m = m0 + wm + mt * 16 + (lane >> 2);
            int n = n0 + wn + nt * 8 + 2 * (lane & 3);
            if (mode == 0) {
                *(float2*)(C + (size_t)m * DMODEL + n) =
                    make_float2(acc[mt][nt][0], acc[mt][nt][1]);
                *(float2*)(C + (size_t)(m + 8) * DMODEL + n) =
                    make_float2(acc[mt][nt][2], acc[mt][nt][3]);
            } else {
                size_t base = ((size_t)(n >> 6) * SEQ + m) * 64 + (n & 63);
                *(float2*)(C + base) = make_float2(acc[mt][nt][0], acc[mt][nt][1]);
                *(float2*)(C + base + 8 * 64) = make_float2(acc[mt][nt][2], acc[mt][nt][3]);
            }
        }
    }
}

// ====================== flash attention (f32x2 + f16x2 exp) =================
#define FA_SMEM_FLOATS (3 * 64 * 64 + 64 * 66)
#define FA_SMEM_BYTES  (FA_SMEM_FLOATS * 4)
#define TSCL 0.1803368801f   /* 0.125 * log2(e): scores in base-2 units */

__global__ __launch_bounds__(256) void flash_kernel(
    const float* __restrict__ Q, const float* __restrict__ K,
    const float* __restrict__ V, float* __restrict__ Z)
{
    extern __shared__ float sm[];
    float* Qs = sm;              // [q][e]   natural, stride 64
    float* Ks = sm + 4096;       // [kr][e]  xor-swizzled e2 cols
    float* Vt = sm + 8192;       // [e][kr]  xor-swizzled kr2 cols
    float* Ps = sm + 12288;      // [q][kr]  natural, stride 66

    const int tid = threadIdx.x;
    const int tx = tid & 15;
    const int ty = tid >> 4;
    const int h  = blockIdx.y;
    const int iq = gridDim.x - 1 - blockIdx.x;

    const float* Qh = Q + ((size_t)h * SEQ + iq * 64) * 64;
#pragma unroll
    for (int r = 0; r < 4; ++r) {
        int idx = tid + r * 256;
        int row = idx >> 4, c4 = idx & 15;
        *(float4*)(Qs + row * 64 + c4 * 4) = *(const float4*)(Qh + row * 64 + c4 * 4);
    }

    float m[4], l[4];
    u64 O2[4][4];
#pragma unroll
    for (int i = 0; i < 4; ++i) {
        m[i] = -1.0e30f; l[i] = 0.0f;
#pragma unroll
        for (int j = 0; j < 4; ++j) O2[i][j] = 0ull;
    }

    for (int jk = 0; jk <= iq; ++jk) {
        __syncthreads();
        const float* Kh = K + ((size_t)h * SEQ + jk * 64) * 64;
        const float* Vh = V + ((size_t)h * SEQ + jk * 64) * 64;
#pragma unroll
        for (int r = 0; r < 4; ++r) {
            int idx = tid + r * 256;
            int row = idx >> 4, c4 = idx & 15;
            float4 kv = *(const float4*)(Kh + row * 64 + c4 * 4);
            int s = (row >> 2) & 15;
            st2s(Ks + row * 64 + (((c4 * 2)     ^ s) * 2), pack2(kv.x, kv.y));
            st2s(Ks + row * 64 + (((c4 * 2 + 1) ^ s) * 2), pack2(kv.z, kv.w));
            float4 vv = *(const float4*)(Vh + row * 64 + c4 * 4);
            int colp = ((row >> 1) ^ (c4 & 15)) * 2 + (row & 1);
            Vt[(c4 * 4 + 0) * 64 + colp] = vv.x;
            Vt[(c4 * 4 + 1) * 64 + colp] = vv.y;
            Vt[(c4 * 4 + 2) * 64 + colp] = vv.z;
            Vt[(c4 * 4 + 3) * 64 + colp] = vv.w;
        }
        __syncthreads();

        u64 acc2[4][4];
#pragma unroll
        for (int i = 0; i < 4; ++i)
#pragma unroll
            for (int j = 0; j < 4; ++j) acc2[i][j] = 0ull;

#pragma unroll 4
        for (int e2 = 0; e2 < 32; ++e2) {
            u64 a2[4], b2[4];
#pragma unroll
            for (int i = 0; i < 4; ++i) a2[i] = ld2s(Qs + (ty * 4 + i) * 64 + e2 * 2);
#pragma unroll
            for (int j = 0; j < 4; ++j) b2[j] = ld2s(Ks + (tx * 4 + j) * 64 + ((e2 ^ tx) * 2));
#pragma unroll
            for (int i = 0; i < 4; ++i)
#pragma unroll
                for (int j = 0; j < 4; ++j) acc2[i][j] = fma2(a2[i], b2[j], acc2[i][j]);
        }

        float sc[4][4];
#pragma unroll
        for (int i = 0; i < 4; ++i)
#pragma unroll
            for (int j = 0; j < 4; ++j) sc[i][j] = hsum2(acc2[i][j]) * TSCL;

        if (jk == iq) {
#pragma unroll
            for (int i = 0; i < 4; ++i)
#pragma unroll
                for (int j = 0; j < 4; ++j)
                    if ((tx * 4 + j) > (ty * 4 + i)) sc[i][j] = -1.0e30f;
        }

        float pm[4];
#pragma unroll
        for (int i = 0; i < 4; ++i)
            pm[i] = fmaxf(fmaxf(sc[i][0], sc[i][1]), fmaxf(sc[i][2], sc[i][3]));
#pragma unroll
        for (int off = 8; off >= 1; off >>= 1)
#pragma unroll
            for (int i = 0; i < 4; ++i)
                pm[i] = fmaxf(pm[i], __shfl_xor_sync(0xffffffffu, pm[i], off));

        float al[4];
#pragma unroll
        for (int i = 0; i < 4; ++i) {
            float mn = fmaxf(m[i], pm[i]);
            al[i] = ex2f(m[i] - mn);     // base-2 rescale, fp32 MUFU
            m[i] = mn;
        }

        float p[4][4], rs[4];
#pragma unroll
        for (int i = 0; i < 4; ++i) {
            exp2_pair(sc[i][0] - m[i], sc[i][1] - m[i], p[i][0], p[i][1]);
            exp2_pair(sc[i][2] - m[i], sc[i][3] - m[i], p[i][2], p[i][3]);
            rs[i] = (p[i][0] + p[i][1]) + (p[i][2] + p[i][3]);
        }
#pragma unroll
        for (int off = 8; off >= 1; off >>= 1)
#pragma unroll
            for (int i = 0; i < 4; ++i)
                rs[i] += __shfl_xor_sync(0xffffffffu, rs[i], off);

#pragma unroll
        for (int i = 0; i < 4; ++i) {
            l[i] = l[i] * al[i] + rs[i];
            u64 al2 = pack2(al[i], al[i]);
#pragma unroll
            for (int j = 0; j < 4; ++j) O2[i][j] = mul2(O2[i][j], al2);
        }

#pragma unroll
        for (int i = 0; i < 4; ++i)
#pragma unroll
            for (int j2 = 0; j2 < 2; ++j2)
                st2s(Ps + (ty * 4 + i) * 66 + tx * 4 + j2 * 2,
                     pack2(p[i][2 * j2], p[i][2 * j2 + 1]));
        __syncthreads();

#pragma unroll 4
        for (int kr2 = 0; kr2 < 32; ++kr2) {
            u64 a2[4], b2[4];
#pragma unroll
            for (int i = 0; i < 4; ++i) a2[i] = ld2s(Ps + (ty * 4 + i) * 66 + kr2 * 2);
#pragma unroll
            for (int j = 0; j < 4; ++j) b2[j] = ld2s(Vt + (tx * 4 + j) * 64 + ((kr2 ^ tx) * 2));
#pragma unroll
            for (int i = 0; i < 4; ++i)
#pragma unroll
                for (int j = 0; j < 4; ++j) O2[i][j] = fma2(a2[i], b2[j], O2[i][j]);
        }
    }

#pragma unroll
    for (int i = 0; i < 4; ++i) {
        float inv = 1.0f / l[i];
        int s = iq * 64 + ty * 4 + i;
#pragma unroll
        for (int j = 0; j < 4; ++j)
            Z[(size_t)s * DMODEL + h * 64 + tx * 4 + j] = hsum2(O2[i][j]) * inv;
    }
}

// ---------------------------------------------------------------------------
extern "C" void kernel_launch(void* const* d_in, const int* in_sizes, int n_in,
                              void* d_out, int out_size)
{
    const float* x   = (const float*)d_in[0];
    const float* W_K = (const float*)d_in[1];
    const float* W_Q = (const float*)d_in[2];
    const float* W_V = (const float*)d_in[3];
    const float* W_O = (const float*)d_in[4];
    float* out = (float*)d_out;

    float *q, *k, *v, *z;
    cudaGetSymbolAddress((void**)&q, g_q);
    cudaGetSymbolAddress((void**)&k, g_k);
    cudaGetSymbolAddress((void**)&v, g_v);
    cudaGetSymbolAddress((void**)&z, g_z);
    __nv_bfloat16 *xh, *xl, *zh, *zl, *wqh, *wql, *wkh, *wkl, *wvh, *wvl, *woh, *wol;
    cudaGetSymbolAddress((void**)&xh, g_xh);   cudaGetSymbolAddress((void**)&xl, g_xl);
    cudaGetSymbolAddress((void**)&zh, g_zh);   cudaGetSymbolAddress((void**)&zl, g_zl);
    cudaGetSymbolAddress((void**)&wqh, g_wqh); cudaGetSymbolAddress((void**)&wql, g_wql);
    cudaGetSymbolAddress((void**)&wkh, g_wkh); cudaGetSymbolAddress((void**)&wkl, g_wkl);
    cudaGetSymbolAddress((void**)&wvh, g_wvh); cudaGetSymbolAddress((void**)&wvl, g_wvl);
    cudaGetSymbolAddress((void**)&woh, g_woh); cudaGetSymbolAddress((void**)&wol, g_wol);

    cudaFuncSetAttribute(flash_kernel,
                         cudaFuncAttributeMaxDynamicSharedMemorySize, FA_SMEM_BYTES);

    const int NX4 = SEQ * DMODEL / 4;
    const int NW4 = DMODEL * DMODEL / 4;

    split_kernel<<<NX4 / 256, 256>>>(x, xh, xl, NX4);
    split_kernel<<<NW4 / 256, 256>>>(W_Q, wqh, wql, NW4);
    split_kernel<<<NW4 / 256, 256>>>(W_K, wkh, wkl, NW4);
    split_kernel<<<NW4 / 256, 256>>>(W_V, wvh, wvl, NW4);

    dim3 gg(SEQ / 128, DMODEL / 128);  // (32, 8)
    gemm_mma<<<gg, 256>>>(xh, xl, wqh, wql, q, 1);
    gemm_mma<<<gg, 256>>>(xh, xl, wkh, wkl, k, 1);
    gemm_mma<<<gg, 256>>>(xh, xl, wvh, wvl, v, 1);

    flash_kernel<<<dim3(SEQ / 64, NHEAD), 256, FA_SMEM_BYTES>>>(q, k, v, z);

    split_kernel<<<NX4 / 256, 256>>>(z, zh, zl, NX4);
    split_kernel<<<NW4 / 256, 256>>>(W_O, woh, wol, NW4);
    gemm_mma<<<gg, 256>>>(zh, zl, woh, wol, out, 0);
}

// round 9
// speedup vs baseline: 2.9901x; 1.8640x over previous
#include <cuda_runtime.h>
#include <cuda_bf16.h>
#include <cstdint>
#include <math.h>

#define SEQ    4096
#define DMODEL 1024
#define NHEAD  16
#define DHEAD  64

typedef unsigned long long u64;
typedef __nv_bfloat16 bf16;

__device__ __forceinline__ uint32_t smem_u32(const void* p) {
    uint32_t a;
    asm("{ .reg .u64 t; cvta.to.shared.u64 t, %1; cvt.u32.u64 %0, t; }" : "=r"(a) : "l"(p));
    return a;
}
__device__ __forceinline__ void ldsm_x4(uint32_t* r, uint32_t addr) {
    asm volatile("ldmatrix.sync.aligned.m8n8.x4.shared.b16 {%0,%1,%2,%3}, [%4];"
        : "=r"(r[0]), "=r"(r[1]), "=r"(r[2]), "=r"(r[3]) : "r"(addr));
}
__device__ __forceinline__ void mma_bf16(float* c, const uint32_t* a, const uint32_t* b) {
    asm volatile(
        "mma.sync.aligned.m16n8k16.row.col.f32.bf16.bf16.f32 "
        "{%0,%1,%2,%3}, {%4,%5,%6,%7}, {%8,%9}, {%0,%1,%2,%3};"
        : "+f"(c[0]), "+f"(c[1]), "+f"(c[2]), "+f"(c[3])
        : "r"(a[0]), "r"(a[1]), "r"(a[2]), "r"(a[3]), "r"(b[0]), "r"(b[1]));
}
__device__ __forceinline__ float ex2f(float x) {
    float y; asm("ex2.approx.f32 %0,%1;" : "=f"(y) : "f"(x)); return y;
}
// pack two floats to bf16x2 (lo first)
__device__ __forceinline__ uint32_t packbf2(float lo, float hi) {
    uint32_t d; asm("cvt.rn.bf16x2.f32 %0,%1,%2;" : "=r"(d) : "f"(hi), "f"(lo)); return d;
}
__device__ __forceinline__ float bf16rt(float x) {
    return __bfloat162float(__float2bfloat16(x));
}

#define CP_ASYNC16(dst, src) \
    asm volatile("cp.async.cg.shared.global [%0],[%1],16;" :: "r"(dst), "l"(src))
#define CP_COMMIT()  asm volatile("cp.async.commit_group;")
#define CP_WAIT(n)   asm volatile("cp.async.wait_group %0;" :: "n"(n))

// ========================= scratch (__device__ globals) =====================
__device__ bf16 g_qh[(size_t)NHEAD * SEQ * DHEAD], g_ql[(size_t)NHEAD * SEQ * DHEAD];
__device__ bf16 g_kh[(size_t)NHEAD * SEQ * DHEAD], g_kl[(size_t)NHEAD * SEQ * DHEAD];
__device__ bf16 g_vth[(size_t)NHEAD * SEQ * DHEAD], g_vtl[(size_t)NHEAD * SEQ * DHEAD];
__device__ bf16 g_zh[(size_t)SEQ * DMODEL], g_zl[(size_t)SEQ * DMODEL];
__device__ bf16 g_xh[(size_t)SEQ * DMODEL], g_xl[(size_t)SEQ * DMODEL];
__device__ bf16 g_wqh[DMODEL * DMODEL], g_wql[DMODEL * DMODEL];
__device__ bf16 g_wkh[DMODEL * DMODEL], g_wkl[DMODEL * DMODEL];
__device__ bf16 g_wvh[DMODEL * DMODEL], g_wvl[DMODEL * DMODEL];
__device__ bf16 g_woh[DMODEL * DMODEL], g_wol[DMODEL * DMODEL];

// ============================ split kernel ==================================
__global__ __launch_bounds__(256) void split_kernel(
    const float* __restrict__ in, bf16* __restrict__ hi,
    bf16* __restrict__ lo, int n4)
{
    int i = blockIdx.x * 256 + threadIdx.x;
    if (i >= n4) return;
    float4 v = ((const float4*)in)[i];
    uint32_t* H = (uint32_t*)hi;
    uint32_t* L = (uint32_t*)lo;
    H[2 * i]     = packbf2(v.x, v.y);
    H[2 * i + 1] = packbf2(v.z, v.w);
    L[2 * i]     = packbf2(v.x - bf16rt(v.x), v.y - bf16rt(v.y));
    L[2 * i + 1] = packbf2(v.z - bf16rt(v.z), v.w - bf16rt(v.w));
}

// ================= mma.sync bf16 GEMM (3-term split, cp.async 2-stage) ======
// modes: 0 -> fp32 C [m][1024]
//        1 -> bf16 split Ch/Cl at [H][S][64]
//        2 -> bf16 split Ch/Cl transposed per head: [H][64][S]
#define GSTR 40
#define GBUF (128 * GSTR)
#define NITER 96

__global__ __launch_bounds__(256) void gemm_mma(
    const bf16* __restrict__ Ah, const bf16* __restrict__ Al,
    const bf16* __restrict__ Bh, const bf16* __restrict__ Bl,
    float* __restrict__ C, bf16* __restrict__ Ch, bf16* __restrict__ Cl, int mode)
{
    __shared__ bf16 As[2][GBUF];
    __shared__ bf16 Bs[2][GBUF];

    const int tid  = threadIdx.x;
    const int warp = tid >> 5, lane = tid & 31;
    const int wm = (warp & 3) * 32;
    const int wn = (warp >> 2) * 64;
    const int m0 = blockIdx.x * 128;
    const int n0 = blockIdx.y * 128;

    const uint32_t as_base = smem_u32(As);
    const uint32_t bs_base = smem_u32(Bs);
    const uint32_t a_addr0 = as_base + ((wm + (lane & 15)) * GSTR + (lane >> 4) * 8) * 2;
    const uint32_t b_addr0 = bs_base +
        ((wn + (lane & 7) + ((lane >> 4) * 8)) * GSTR + (((lane >> 3) & 1) * 8)) * 2;

    const int crow0 = tid >> 2, ccol = (tid & 3) * 8;
    const int crow1 = (tid + 256) >> 2;

    const bf16* Aps[3]; const bf16* Bps[3];
    Aps[0] = Ah; Bps[0] = Bh;  Aps[1] = Ah; Bps[1] = Bl;  Aps[2] = Al; Bps[2] = Bh;

    float acc[2][8][4];
#pragma unroll
    for (int i = 0; i < 2; ++i)
#pragma unroll
        for (int j = 0; j < 8; ++j)
#pragma unroll
            for (int t = 0; t < 4; ++t) acc[i][j][t] = 0.0f;

    {
        const bf16* Ap = Aps[0]; const bf16* Bp = Bps[0];
        CP_ASYNC16(as_base + (crow0 * GSTR + ccol) * 2, Ap + (size_t)(m0 + crow0) * DMODEL + ccol);
        CP_ASYNC16(as_base + (crow1 * GSTR + ccol) * 2, Ap + (size_t)(m0 + crow1) * DMODEL + ccol);
        CP_ASYNC16(bs_base + (crow0 * GSTR + ccol) * 2, Bp + (size_t)(n0 + crow0) * DMODEL + ccol);
        CP_ASYNC16(bs_base + (crow1 * GSTR + ccol) * 2, Bp + (size_t)(n0 + crow1) * DMODEL + ccol);
        CP_COMMIT();
    }

#pragma unroll 1
    for (int c = 0; c < NITER; ++c) {
        const int buf = c & 1;
        if (c + 1 < NITER) {
            const int cn = c + 1;
            const bf16* Ap = Aps[cn >> 5];
            const bf16* Bp = Bps[cn >> 5];
            const int k0 = (cn & 31) * 32;
            const uint32_t ao = as_base + (cn & 1) * GBUF * 2;
            const uint32_t bo = bs_base + (cn & 1) * GBUF * 2;
            CP_ASYNC16(ao + (crow0 * GSTR + ccol) * 2, Ap + (size_t)(m0 + crow0) * DMODEL + k0 + ccol);
            CP_ASYNC16(ao + (crow1 * GSTR + ccol) * 2, Ap + (size_t)(m0 + crow1) * DMODEL + k0 + ccol);
            CP_ASYNC16(bo + (crow0 * GSTR + ccol) * 2, Bp + (size_t)(n0 + crow0) * DMODEL + k0 + ccol);
            CP_ASYNC16(bo + (crow1 * GSTR + ccol) * 2, Bp + (size_t)(n0 + crow1) * DMODEL + k0 + ccol);
            CP_COMMIT();
            CP_WAIT(1);
        } else {
            CP_WAIT(0);
        }
        __syncthreads();

        const uint32_t abuf = buf * GBUF * 2;
#pragma unroll
        for (int kk = 0; kk < 2; ++kk) {
            uint32_t a[2][4], b[8][2];
#pragma unroll
            for (int mt = 0; mt < 2; ++mt)
                ldsm_x4(a[mt], a_addr0 + abuf + (mt * 16 * GSTR + kk * 16) * 2);
#pragma unroll
            for (int j = 0; j < 4; ++j) {
                uint32_t r[4];
                ldsm_x4(r, b_addr0 + abuf + (j * 16 * GSTR + kk * 16) * 2);
                b[j * 2][0] = r[0]; b[j * 2][1] = r[1];
                b[j * 2 + 1][0] = r[2]; b[j * 2 + 1][1] = r[3];
            }
#pragma unroll
            for (int mt = 0; mt < 2; ++mt)
#pragma unroll
                for (int nt = 0; nt < 8; ++nt)
                    mma_bf16(acc[mt][nt], a[mt], b[nt]);
        }
        __syncthreads();
    }

#pragma unroll
    for (int mt = 0; mt < 2; ++mt) {
#pragma unroll
        for (int nt = 0; nt < 8; ++nt) {
            int m = m0 + wm + mt * 16 + (lane >> 2);
            int n = n0 + wn + nt * 8 + 2 * (lane & 3);
            float c0 = acc[mt][nt][0], c1 = acc[mt][nt][1];
            float c2 = acc[mt][nt][2], c3 = acc[mt][nt][3];
            if (mode == 0) {
                *(float2*)(C + (size_t)m * DMODEL + n) = make_float2(c0, c1);
                *(float2*)(C + (size_t)(m + 8) * DMODEL + n) = make_float2(c2, c3);
            } else if (mode == 1) {
                size_t i0 = ((size_t)(n >> 6) * SEQ + m) * 64 + (n & 63);
                *(uint32_t*)(Ch + i0) = packbf2(c0, c1);
                *(uint32_t*)(Cl + i0) = packbf2(c0 - bf16rt(c0), c1 - bf16rt(c1));
                *(uint32_t*)(Ch + i0 + 8 * 64) = packbf2(c2, c3);
                *(uint32_t*)(Cl + i0 + 8 * 64) = packbf2(c2 - bf16rt(c2), c3 - bf16rt(c3));
            } else {
                // transposed per head: [(h)][e][s]
                size_t b0 = ((size_t)(n >> 6) * 64 + (n & 63)) * SEQ;
                Ch[b0 + m] = __float2bfloat16(c0);
                Cl[b0 + m] = __float2bfloat16(c0 - bf16rt(c0));
                Ch[b0 + m + 8] = __float2bfloat16(c2);
                Cl[b0 + m + 8] = __float2bfloat16(c2 - bf16rt(c2));
                Ch[b0 + SEQ + m] = __float2bfloat16(c1);
                Cl[b0 + SEQ + m] = __float2bfloat16(c1 - bf16rt(c1));
                Ch[b0 + SEQ + m + 8] = __float2bfloat16(c3);
                Cl[b0 + SEQ + m + 8] = __float2bfloat16(c3 - bf16rt(c3));
            }
        }
    }
}

// ================ flash attention on mma.sync (bf16 split) ==================
// CTA: 128 q-rows x 1 head, 8 warps (warp = 16 q rows). K-blocks of 64.
// Smem (bf16 elems, row stride 72):
//   [0)        qh tile  128x72
//   [9216)     ql tile  128x72
//   [18432)    2 stages x { kh, kl, vth, vtl } each 64x72
#define FSTR 72
#define SQL  (128 * FSTR)
#define SKV  (2 * 128 * FSTR)
#define STG  (4 * 64 * FSTR)
#define OKL  (64 * FSTR)
#define OVH  (2 * 64 * FSTR)
#define OVL  (3 * 64 * FSTR)
#define FA_SMEM_BYTES ((SKV + 2 * STG) * 2)   // 110592
#define TSCL 0.1803368801f                    // 0.125 * log2(e)

__global__ __launch_bounds__(256) void flash_mma(
    const bf16* __restrict__ Qh, const bf16* __restrict__ Ql,
    const bf16* __restrict__ Kh, const bf16* __restrict__ Kl,
    const bf16* __restrict__ Vth, const bf16* __restrict__ Vtl,
    bf16* __restrict__ Zh, bf16* __restrict__ Zl)
{
    extern __shared__ bf16 sm[];
    const uint32_t sbase = smem_u32(sm);
    const int tid = threadIdx.x;
    const int warp = tid >> 5, lane = tid & 31;
    const int wm = warp * 16;
    const int h  = blockIdx.y;
    const int iq = gridDim.x - 1 - blockIdx.x;   // big work first

    // ---- load Q tiles (hi & lo), 4 uint4 per thread per tile ----
    {
        const size_t qoff = ((size_t)h * SEQ + iq * 128) * 64;
#pragma unroll
        for (int it = 0; it < 4; ++it) {
            int idx = tid + it * 256;
            int row = idx >> 3, c8 = idx & 7;
            *(uint4*)(sm + row * FSTR + c8 * 8) =
                *(const uint4*)(Qh + qoff + (size_t)row * 64 + c8 * 8);
            *(uint4*)(sm + SQL + row * FSTR + c8 * 8) =
                *(const uint4*)(Ql + qoff + (size_t)row * 64 + c8 * 8);
        }
    }
    __syncthreads();

    // Q fragments (register-resident for whole kernel)
    uint32_t qfh[4][4], qfl[4][4];
    {
        const uint32_t aq = sbase + ((wm + (lane & 15)) * FSTR + (lane >> 4) * 8) * 2;
#pragma unroll
        for (int kt = 0; kt < 4; ++kt) {
            ldsm_x4(qfh[kt], aq + kt * 32);
            ldsm_x4(qfl[kt], aq + SQL * 2 + kt * 32);
        }
    }
    __syncthreads();

    float m0 = -1.0e30f, m1 = -1.0e30f, l0 = 0.0f, l1 = 0.0f;
    float oa[8][4];
#pragma unroll
    for (int j = 0; j < 8; ++j)
#pragma unroll
        for (int t = 0; t < 4; ++t) oa[j][t] = 0.0f;

    const int nblk = 2 * iq + 2;
    const int c_row = tid >> 3, c_c8 = tid & 7;          // copy mapping (x2 iters)
    const size_t kvh = (size_t)h * SEQ * 64;

    // prologue: stage 0
    {
        const uint32_t dst = sbase + SKV * 2;
        const size_t ks = kvh + (size_t)c_row * 64 + c_c8 * 8;
        const size_t vs = ((size_t)h * 64 + c_row) * SEQ + c_c8 * 8;
#pragma unroll
        for (int it = 0; it < 2; ++it) {
            int row = c_row + it * 32;
            uint32_t d = dst + (row * FSTR + c_c8 * 8) * 2;
            size_t k2 = ks + (size_t)it * 32 * 64;
            size_t v2 = vs + (size_t)it * 32 * SEQ;
            CP_ASYNC16(d,            Kh  + k2);
            CP_ASYNC16(d + OKL * 2,  Kl  + k2);
            CP_ASYNC16(d + OVH * 2,  Vth + v2);
            CP_ASYNC16(d + OVL * 2,  Vtl + v2);
        }
        CP_COMMIT();
    }

#pragma unroll 1
    for (int jk = 0; jk < nblk; ++jk) {
        const int st = jk & 1;
        if (jk + 1 < nblk) {
            const int jn = jk + 1;
            const uint32_t dst = sbase + (SKV + (jn & 1) * STG) * 2;
            const size_t ks = kvh + ((size_t)jn * 64 + c_row) * 64 + c_c8 * 8;
            const size_t vs = ((size_t)h * 64 + c_row) * SEQ + jn * 64 + c_c8 * 8;
#pragma unroll
            for (int it = 0; it < 2; ++it) {
                int row = c_row + it * 32;
                uint32_t d = dst + (row * FSTR + c_c8 * 8) * 2;
                size_t k2 = ks + (size_t)it * 32 * 64;
                size_t v2 = vs + (size_t)it * 32 * SEQ;
                CP_ASYNC16(d,            Kh  + k2);
                CP_ASYNC16(d + OKL * 2,  Kl  + k2);
                CP_ASYNC16(d + OVH * 2,  Vth + v2);
                CP_ASYNC16(d + OVL * 2,  Vtl + v2);
            }
            CP_COMMIT();
            CP_WAIT(1);
        } else {
            CP_WAIT(0);
        }
        __syncthreads();

        const uint32_t kbase = sbase + (SKV + st * STG) * 2;
        const uint32_t brow = (lane & 7) + ((lane >> 4) * 8);
        const uint32_t bcol = ((lane >> 3) & 1) * 8;

        // ---- S = Q K^T (3-term split) ----
        float sa[8][4];
#pragma unroll
        for (int j = 0; j < 8; ++j)
#pragma unroll
            for (int t = 0; t < 4; ++t) sa[j][t] = 0.0f;

#pragma unroll
        for (int j = 0; j < 4; ++j) {
            const uint32_t rb = kbase + ((j * 16 + brow) * FSTR + bcol) * 2;
#pragma unroll
            for (int kt = 0; kt < 4; ++kt) {
                uint32_t bh[4], bl[4];
                ldsm_x4(bh, rb + kt * 32);
                ldsm_x4(bl, rb + OKL * 2 + kt * 32);
                mma_bf16(sa[2 * j],     qfh[kt], bh);
                mma_bf16(sa[2 * j + 1], qfh[kt], bh + 2);
                mma_bf16(sa[2 * j],     qfl[kt], bh);
                mma_bf16(sa[2 * j + 1], qfl[kt], bh + 2);
                mma_bf16(sa[2 * j],     qfh[kt], bl);
                mma_bf16(sa[2 * j + 1], qfh[kt], bl + 2);
            }
        }

        // ---- scale + causal mask ----
        const bool diag = (jk >= 2 * iq);
        const int r0 = iq * 128 + wm + (lane >> 2);
#pragma unroll
        for (int nt = 0; nt < 8; ++nt) {
#pragma unroll
            for (int cc = 0; cc < 4; ++cc) {
                float s = sa[nt][cc] * TSCL;
                if (diag) {
                    int col = jk * 64 + nt * 8 + 2 * (lane & 3) + (cc & 1);
                    int row = r0 + ((cc >= 2) ? 8 : 0);
                    if (col > row) s = -1.0e30f;
                }
                sa[nt][cc] = s;
            }
        }

        // ---- online softmax ----
        float pm0 = -1.0e30f, pm1 = -1.0e30f;
#pragma unroll
        for (int nt = 0; nt < 8; ++nt) {
            pm0 = fmaxf(pm0, fmaxf(sa[nt][0], sa[nt][1]));
            pm1 = fmaxf(pm1, fmaxf(sa[nt][2], sa[nt][3]));
        }
        pm0 = fmaxf(pm0, __shfl_xor_sync(0xffffffffu, pm0, 1));
        pm0 = fmaxf(pm0, __shfl_xor_sync(0xffffffffu, pm0, 2));
        pm1 = fmaxf(pm1, __shfl_xor_sync(0xffffffffu, pm1, 1));
        pm1 = fmaxf(pm1, __shfl_xor_sync(0xffffffffu, pm1, 2));

        float mn0 = fmaxf(m0, pm0), mn1 = fmaxf(m1, pm1);
        float al0 = ex2f(m0 - mn0), al1 = ex2f(m1 - mn1);
        m0 = mn0; m1 = mn1;

        float rs0 = 0.0f, rs1 = 0.0f;
#pragma unroll
        for (int nt = 0; nt < 8; ++nt) {
            float p0 = ex2f(sa[nt][0] - m0);
            float p1 = ex2f(sa[nt][1] - m0);
            float p2 = ex2f(sa[nt][2] - m1);
            float p3 = ex2f(sa[nt][3] - m1);
            sa[nt][0] = p0; sa[nt][1] = p1; sa[nt][2] = p2; sa[nt][3] = p3;
            rs0 += p0 + p1; rs1 += p2 + p3;
        }
        rs0 += __shfl_xor_sync(0xffffffffu, rs0, 1);
        rs0 += __shfl_xor_sync(0xffffffffu, rs0, 2);
        rs1 += __shfl_xor_sync(0xffffffffu, rs1, 1);
        rs1 += __shfl_xor_sync(0xffffffffu, rs1, 2);
        l0 = l0 * al0 + rs0;
        l1 = l1 * al1 + rs1;
#pragma unroll
        for (int nt = 0; nt < 8; ++nt) {
            oa[nt][0] *= al0; oa[nt][1] *= al0;
            oa[nt][2] *= al1; oa[nt][3] *= al1;
        }

        // ---- O += P V (ph*vh + pl*vh + ph*vl) ----
#pragma unroll
        for (int kt = 0; kt < 4; ++kt) {
            uint32_t pfh[4], pfl[4];
            {
                float a0 = sa[2 * kt][0], a1 = sa[2 * kt][1];
                float a2 = sa[2 * kt][2], a3 = sa[2 * kt][3];
                float b0 = sa[2 * kt + 1][0], b1 = sa[2 * kt + 1][1];
                float b2 = sa[2 * kt + 1][2], b3 = sa[2 * kt + 1][3];
                pfh[0] = packbf2(a0, a1);  pfh[1] = packbf2(a2, a3);
                pfh[2] = packbf2(b0, b1);  pfh[3] = packbf2(b2, b3);
                pfl[0] = packbf2(a0 - bf16rt(a0), a1 - bf16rt(a1));
                pfl[1] = packbf2(a2 - bf16rt(a2), a3 - bf16rt(a3));
                pfl[2] = packbf2(b0 - bf16rt(b0), b1 - bf16rt(b1));
                pfl[3] = packbf2(b2 - bf16rt(b2), b3 - bf16rt(b3));
            }
#pragma unroll
            for (int j = 0; j < 4; ++j) {
                const uint32_t vb = kbase + (OVH + (j * 16 + brow) * FSTR + bcol) * 2 + kt * 32;
                uint32_t vh[4], vl[4];
                ldsm_x4(vh, vb);
                ldsm_x4(vl, vb + (OVL - OVH) * 2);
                mma_bf16(oa[2 * j],     pfh, vh);
                mma_bf16(oa[2 * j + 1], pfh, vh + 2);
                mma_bf16(oa[2 * j],     pfl, vh);
                mma_bf16(oa[2 * j + 1], pfl, vh + 2);
                mma_bf16(oa[2 * j],     pfh, vl);
                mma_bf16(oa[2 * j + 1], pfh, vl + 2);
            }
        }
        __syncthreads();
    }

    // ---- epilogue: normalize + write zh/zl splits ----
    const float inv0 = 1.0f / l0, inv1 = 1.0f / l1;
    const int s0 = iq * 128 + wm + (lane >> 2);
    const size_t b0 = (size_t)s0 * DMODEL + h * 64;
    const size_t b1 = b0 + 8 * DMODEL;
#pragma unroll
    for (int nt = 0; nt < 8; ++nt) {
        int e = nt * 8 + 2 * (lane & 3);
        float a0 = oa[nt][0] * inv0, a1 = oa[nt][1] * inv0;
        float a2 = oa[nt][2] * inv1, a3 = oa[nt][3] * inv1;
        *(uint32_t*)(Zh + b0 + e) = packbf2(a0, a1);
        *(uint32_t*)(Zl + b0 + e) = packbf2(a0 - bf16rt(a0), a1 - bf16rt(a1));
        *(uint32_t*)(Zh + b1 + e) = packbf2(a2, a3);
        *(uint32_t*)(Zl + b1 + e) = packbf2(a2 - bf16rt(a2), a3 - bf16rt(a3));
    }
}

// ---------------------------------------------------------------------------
extern "C" void kernel_launch(void* const* d_in, const int* in_sizes, int n_in,
                              void* d_out, int out_size)
{
    const float* x   = (const float*)d_in[0];
    const float* W_K = (const float*)d_in[1];
    const float* W_Q = (const float*)d_in[2];
    const float* W_V = (const float*)d_in[3];
    const float* W_O = (const float*)d_in[4];
    float* out = (float*)d_out;

    bf16 *qh, *ql, *kh, *kl, *vth, *vtl, *zh, *zl, *xh, *xl;
    bf16 *wqh, *wql, *wkh, *wkl, *wvh, *wvl, *woh, *wol;
    cudaGetSymbolAddress((void**)&qh, g_qh);   cudaGetSymbolAddress((void**)&ql, g_ql);
    cudaGetSymbolAddress((void**)&kh, g_kh);   cudaGetSymbolAddress((void**)&kl, g_kl);
    cudaGetSymbolAddress((void**)&vth, g_vth); cudaGetSymbolAddress((void**)&vtl, g_vtl);
    cudaGetSymbolAddress((void**)&zh, g_zh);   cudaGetSymbolAddress((void**)&zl, g_zl);
    cudaGetSymbolAddress((void**)&xh, g_xh);   cudaGetSymbolAddress((void**)&xl, g_xl);
    cudaGetSymbolAddress((void**)&wqh, g_wqh); cudaGetSymbolAddress((void**)&wql, g_wql);
    cudaGetSymbolAddress((void**)&wkh, g_wkh); cudaGetSymbolAddress((void**)&wkl, g_wkl);
    cudaGetSymbolAddress((void**)&wvh, g_wvh); cudaGetSymbolAddress((void**)&wvl, g_wvl);
    cudaGetSymbolAddress((void**)&woh, g_woh); cudaGetSymbolAddress((void**)&wol, g_wol);

    cudaFuncSetAttribute(flash_mma,
                         cudaFuncAttributeMaxDynamicSharedMemorySize, FA_SMEM_BYTES);

    const int NX4 = SEQ * DMODEL / 4;
    const int NW4 = DMODEL * DMODEL / 4;

    split_kernel<<<NX4 / 256, 256>>>(x, xh, xl, NX4);
    split_kernel<<<NW4 / 256, 256>>>(W_Q, wqh, wql, NW4);
    split_kernel<<<NW4 / 256, 256>>>(W_K, wkh, wkl, NW4);
    split_kernel<<<NW4 / 256, 256>>>(W_V, wvh, wvl, NW4);
    split_kernel<<<NW4 / 256, 256>>>(W_O, woh, wol, NW4);

    dim3 gg(SEQ / 128, DMODEL / 128);  // (32, 8)
    gemm_mma<<<gg, 256>>>(xh, xl, wqh, wql, nullptr, qh, ql, 1);
    gemm_mma<<<gg, 256>>>(xh, xl, wkh, wkl, nullptr, kh, kl, 1);
    gemm_mma<<<gg, 256>>>(xh, xl, wvh, wvl, nullptr, vth, vtl, 2);

    flash_mma<<<dim3(SEQ / 128, NHEAD), 256, FA_SMEM_BYTES>>>(
        qh, ql, kh, kl, vth, vtl, zh, zl);

    gemm_mma<<<gg, 256>>>(zh, zl, woh, wol, out, nullptr, nullptr, 0);
}